// round 3
// baseline (speedup 1.0000x reference)
#include <cuda_runtime.h>
#include <cstdint>

#define HEADS 16
#define HIDDEN 1024
#define DH 64
#define SK 72                 // smem row stride (words); 72 mod 32 = 8 -> LDS.64 conflict-free
#define QSCALE 0.03125f       // 1/sqrt(1024)
#define NEGBIG (-1e9f)
#define SEQ 2048

__device__ __forceinline__ uint32_t f2tf(float f) {
    uint32_t r; asm("cvt.rna.tf32.f32 %0, %1;" : "=r"(r) : "f"(f)); return r;
}

__device__ __forceinline__ void mma8(float* c,
                                     uint32_t a0, uint32_t a1, uint32_t a2, uint32_t a3,
                                     uint32_t b0, uint32_t b1) {
    asm volatile("mma.sync.aligned.m16n8k8.row.col.f32.tf32.tf32.f32 "
                 "{%0,%1,%2,%3},{%4,%5,%6,%7},{%8,%9},{%0,%1,%2,%3};"
                 : "+f"(c[0]), "+f"(c[1]), "+f"(c[2]), "+f"(c[3])
                 : "r"(a0), "r"(a1), "r"(a2), "r"(a3), "r"(b0), "r"(b1));
}

// Flash attention, causal, K/V swapped per reference:
//   scores = Q @ Z^T * scale + NEG*max(causal, 1-pad); out = softmax(scores) @ Y
// q-tile = 128 rows, 4 warps, M=32/warp; k-tile = 64.
__global__ __launch_bounds__(128)
void fa_tf32_kernel(const float* __restrict__ X,   // Q source
                    const float* __restrict__ Y,   // V_eff source
                    const float* __restrict__ Z,   // K_eff source
                    const float* __restrict__ PAD,
                    float* __restrict__ OUT,
                    int S)
{
    extern __shared__ uint32_t sm[];
    uint32_t* Qs = sm;              // [128][SK] tf32, permuted 8-col groups
    uint32_t* Ks = Qs + 128 * SK;   // [64][SK]  tf32, permuted
    uint32_t* Vs = Ks + 64 * SK;    // [64][SK]  tf32, plain layout
    uint32_t* Ps = Vs + 64 * SK;    // [128][SK] tf32, permuted + ^2 swizzle
    float*  padS = (float*)(Ps + 128 * SK);   // [64]

    const int qt  = (gridDim.x - 1) - blockIdx.x;   // heavy CTAs first
    const int h   = blockIdx.y;
    const int b   = blockIdx.z;
    const int tid = threadIdx.x;
    const int w    = tid >> 5;
    const int lane = tid & 31;
    const int g    = lane >> 2;           // 0..7
    const int l4   = lane & 3;            // 0..3
    const int q0   = qt * 128;
    const int rbw  = w * 32;              // warp row base in q-tile
    const int s2   = ((g >> 2) & 1) << 1; // P-store bank swizzle (0 or 2)
    const int pbase = ((l4 & 1) << 2) | (l4 >> 1);   // perm8(2*l4)

    const float* Qg   = X + (size_t)b * S * HIDDEN + h * DH;
    const float* Kg   = Z + (size_t)b * S * HIDDEN + h * DH;   // K_eff = z
    const float* Vg   = Y + (size_t)b * S * HIDDEN + h * DH;   // V_eff = y
    const float* padg = PAD + (size_t)b * S;

    // ---- load + convert Q tile (128 x 64), permuted column layout ----
    #pragma unroll
    for (int it = 0; it < 16; it++) {
        int idx = tid + 128 * it;            // 128 rows x 16 float4
        int row = idx >> 4, c4 = idx & 15;
        float4 v = *(const float4*)(Qg + (size_t)(q0 + row) * HIDDEN + c4 * 4);
        uint32_t* d = Qs + row * SK + (c4 >> 1) * 8 + (c4 & 1);
        d[0] = f2tf(v.x); d[2] = f2tf(v.y); d[4] = f2tf(v.z); d[6] = f2tf(v.w);
    }

    float O[2][8][4];
    float mrow[2][2], lrow[2][2];
    #pragma unroll
    for (int mh = 0; mh < 2; mh++) {
        mrow[mh][0] = mrow[mh][1] = -1e30f;
        lrow[mh][0] = lrow[mh][1] = 0.f;
        #pragma unroll
        for (int nt = 0; nt < 8; nt++)
            #pragma unroll
            for (int j = 0; j < 4; j++) O[mh][nt][j] = 0.f;
    }

    const int nkt = 2 * qt + 2;
    for (int kt = 0; kt < nkt; kt++) {
        __syncthreads();                      // prev iter's Ks/Vs readers done
        const int k0 = kt * 64;

        // ---- load + convert K (permuted) / V (plain) tiles ----
        #pragma unroll
        for (int it = 0; it < 8; it++) {
            int idx = tid + 128 * it;         // 64 rows x 16 float4
            int row = idx >> 4, c4 = idx & 15;
            float4 kv = *(const float4*)(Kg + (size_t)(k0 + row) * HIDDEN + c4 * 4);
            float4 vv = *(const float4*)(Vg + (size_t)(k0 + row) * HIDDEN + c4 * 4);
            uint32_t* dk = Ks + row * SK + (c4 >> 1) * 8 + (c4 & 1);
            dk[0] = f2tf(kv.x); dk[2] = f2tf(kv.y); dk[4] = f2tf(kv.z); dk[6] = f2tf(kv.w);
            uint4 pv;
            pv.x = f2tf(vv.x); pv.y = f2tf(vv.y); pv.z = f2tf(vv.z); pv.w = f2tf(vv.w);
            *(uint4*)(Vs + row * SK + c4 * 4) = pv;
        }
        if (tid < 16)
            *(float4*)(padS + tid * 4) = *(const float4*)(padg + k0 + tid * 4);
        __syncthreads();

        // ---- score GEMM: c[mh] = Q(32x64) @ K^T -> 32x64 per warp ----
        float c[2][8][4];
        #pragma unroll
        for (int mh = 0; mh < 2; mh++)
            #pragma unroll
            for (int nt = 0; nt < 8; nt++)
                #pragma unroll
                for (int j = 0; j < 4; j++) c[mh][nt][j] = 0.f;

        #pragma unroll
        for (int k8 = 0; k8 < 8; k8++) {
            uint32_t a[2][4];
            #pragma unroll
            for (int mh = 0; mh < 2; mh++) {
                int r0 = rbw + mh * 16 + g;
                uint2 t0 = *(uint2*)(Qs + r0 * SK + k8 * 8 + 2 * l4);
                uint2 t1 = *(uint2*)(Qs + (r0 + 8) * SK + k8 * 8 + 2 * l4);
                a[mh][0] = t0.x; a[mh][2] = t0.y;
                a[mh][1] = t1.x; a[mh][3] = t1.y;
            }
            #pragma unroll
            for (int nt = 0; nt < 8; nt++) {
                uint2 bk = *(uint2*)(Ks + (nt * 8 + g) * SK + k8 * 8 + 2 * l4);
                mma8(c[0][nt], a[0][0], a[0][1], a[0][2], a[0][3], bk.x, bk.y);
                mma8(c[1][nt], a[1][0], a[1][1], a[1][2], a[1][3], bk.x, bk.y);
            }
        }

        // ---- scale + mask + online softmax + P store ----
        #pragma unroll
        for (int mh = 0; mh < 2; mh++) {
            #pragma unroll
            for (int h2 = 0; h2 < 2; h2++) {
                const int q = q0 + rbw + mh * 16 + 8 * h2 + g;
                float mx = -1e30f;
                #pragma unroll
                for (int nt = 0; nt < 8; nt++) {
                    #pragma unroll
                    for (int d = 0; d < 2; d++) {
                        int kcl = nt * 8 + 2 * l4 + d;
                        int k = k0 + kcl;
                        float maskv = fmaxf((k > q) ? 1.f : 0.f, 1.f - padS[kcl]);
                        float val = c[mh][nt][2 * h2 + d] * QSCALE + NEGBIG * maskv;
                        c[mh][nt][2 * h2 + d] = val;
                        mx = fmaxf(mx, val);
                    }
                }
                mx = fmaxf(mx, __shfl_xor_sync(0xffffffffu, mx, 1));
                mx = fmaxf(mx, __shfl_xor_sync(0xffffffffu, mx, 2));
                float mnew  = fmaxf(mrow[mh][h2], mx);
                float alpha = __expf(mrow[mh][h2] - mnew);
                mrow[mh][h2] = mnew;

                float rs = 0.f;
                const int prow = rbw + mh * 16 + 8 * h2 + g;
                #pragma unroll
                for (int nt = 0; nt < 8; nt++) {
                    #pragma unroll
                    for (int d = 0; d < 2; d++) {
                        float p = __expf(c[mh][nt][2 * h2 + d] - mnew);
                        rs += p;
                        Ps[prow * SK + nt * 8 + ((pbase + 2 * d) ^ s2)] = f2tf(p);
                    }
                }
                rs += __shfl_xor_sync(0xffffffffu, rs, 1);
                rs += __shfl_xor_sync(0xffffffffu, rs, 2);
                lrow[mh][h2] = lrow[mh][h2] * alpha + rs;

                #pragma unroll
                for (int nt = 0; nt < 8; nt++) {
                    O[mh][nt][2 * h2]     *= alpha;
                    O[mh][nt][2 * h2 + 1] *= alpha;
                }
            }
        }
        __syncwarp();   // P rows are warp-private

        // ---- PV GEMM: O[mh] += P(32x64) @ V(64x64) ----
        #pragma unroll
        for (int k8 = 0; k8 < 8; k8++) {
            uint32_t a[2][4];
            #pragma unroll
            for (int mh = 0; mh < 2; mh++) {
                int r0 = rbw + mh * 16 + g;
                uint2 t0 = *(uint2*)(Ps + r0 * SK + k8 * 8 + ((2 * l4) ^ s2));
                uint2 t1 = *(uint2*)(Ps + (r0 + 8) * SK + k8 * 8 + ((2 * l4) ^ s2));
                a[mh][0] = t0.x; a[mh][2] = t0.y;
                a[mh][1] = t1.x; a[mh][3] = t1.y;
            }
            #pragma unroll
            for (int nt = 0; nt < 8; nt++) {
                uint32_t b0 = Vs[(k8 * 8 + l4) * SK + nt * 8 + g];
                uint32_t b1 = Vs[(k8 * 8 + l4 + 4) * SK + nt * 8 + g];
                mma8(O[0][nt], a[0][0], a[0][1], a[0][2], a[0][3], b0, b1);
                mma8(O[1][nt], a[1][0], a[1][1], a[1][2], a[1][3], b0, b1);
            }
        }
    }

    // ---- epilogue: normalize and store ----
    float* Og = OUT + (size_t)b * S * HIDDEN + h * DH;
    #pragma unroll
    for (int mh = 0; mh < 2; mh++) {
        #pragma unroll
        for (int h2 = 0; h2 < 2; h2++) {
            float inv = 1.f / lrow[mh][h2];
            int row = q0 + rbw + mh * 16 + 8 * h2 + g;
            #pragma unroll
            for (int nt = 0; nt < 8; nt++) {
                float2 o;
                o.x = O[mh][nt][2 * h2]     * inv;
                o.y = O[mh][nt][2 * h2 + 1] * inv;
                *(float2*)(Og + (size_t)row * HIDDEN + nt * 8 + 2 * l4) = o;
            }
        }
    }
}

extern "C" void kernel_launch(void* const* d_in, const int* in_sizes, int n_in,
                              void* d_out, int out_size)
{
    const float* x   = (const float*)d_in[0];
    const float* y   = (const float*)d_in[1];
    const float* z   = (const float*)d_in[2];
    const float* pad = (const float*)d_in[3];
    float* out = (float*)d_out;

    const int S = SEQ;
    const int B = in_sizes[3] / S;

    const size_t smem_bytes = (size_t)(128 + 64 + 64 + 128) * SK * sizeof(uint32_t)
                            + 64 * sizeof(float);          // 110,848 B
    cudaFuncSetAttribute(fa_tf32_kernel,
                         cudaFuncAttributeMaxDynamicSharedMemorySize,
                         (int)smem_bytes);

    dim3 grid(S / 128, HEADS, B);
    fa_tf32_kernel<<<grid, 128, smem_bytes>>>(x, y, z, pad, out, S);
}

// round 4
// speedup vs baseline: 1.0715x; 1.0715x over previous
#include <cuda_runtime.h>
#include <cstdint>

#define HEADS 16
#define HIDDEN 1024
#define DH 64
#define SK 72                 // smem row stride (words); 72 mod 32 = 8 -> conflict-free frags
#define QSCALE 0.03125f       // 1/sqrt(1024)
#define NEGBIG (-1e9f)
#define SEQ 2048

__device__ __forceinline__ uint32_t f2tf(float f) {
    uint32_t r; asm("cvt.rna.tf32.f32 %0, %1;" : "=r"(r) : "f"(f)); return r;
}

__device__ __forceinline__ void mma8(float* c,
                                     uint32_t a0, uint32_t a1, uint32_t a2, uint32_t a3,
                                     uint32_t b0, uint32_t b1) {
    asm volatile("mma.sync.aligned.m16n8k8.row.col.f32.tf32.tf32.f32 "
                 "{%0,%1,%2,%3},{%4,%5,%6,%7},{%8,%9},{%0,%1,%2,%3};"
                 : "+f"(c[0]), "+f"(c[1]), "+f"(c[2]), "+f"(c[3])
                 : "r"(a0), "r"(a1), "r"(a2), "r"(a3), "r"(b0), "r"(b1));
}

// Flash attention, causal, K/V swapped per reference:
//   scores = Q @ Z^T * scale + NEG*max(causal, 1-pad); out = softmax(scores) @ Y
// q-tile = 128 rows, 4 warps, M=32/warp; k-tile = 64. P never touches smem
// (C-fragment -> A-fragment via quad shuffles).
__global__ __launch_bounds__(128, 3)
void fa_tf32_kernel(const float* __restrict__ X,   // Q source
                    const float* __restrict__ Y,   // V_eff source
                    const float* __restrict__ Z,   // K_eff source
                    const float* __restrict__ PAD,
                    float* __restrict__ OUT,
                    int S)
{
    extern __shared__ uint32_t sm[];
    uint32_t* Qs = sm;              // [128][SK] tf32, permuted 8-col groups
    uint32_t* Ks = Qs + 128 * SK;   // [64][SK]  tf32, permuted
    uint32_t* Vs = Ks + 64 * SK;    // [64][SK]  tf32, plain layout
    float*  npS = (float*)(Vs + 64 * SK);   // [64]  NEG*(1-pad)

    const int qt  = (gridDim.x - 1) - blockIdx.x;   // heavy CTAs first
    const int h   = blockIdx.y;
    const int b   = blockIdx.z;
    const int tid = threadIdx.x;
    const int lane = tid & 31;
    const int g    = lane >> 2;           // 0..7
    const int l4   = lane & 3;            // 0..3
    const int q0   = qt * 128;
    const int rbw  = (tid >> 5) * 32;     // warp row base in q-tile
    const int src0 = (lane & ~3) | (l4 >> 1);   // shuffle sources for P frag
    const int src2 = src0 + 2;
    const bool dsel = (l4 & 1);

    const float* Qg   = X + (size_t)b * S * HIDDEN + h * DH;
    const float* Kg   = Z + (size_t)b * S * HIDDEN + h * DH;   // K_eff = z
    const float* Vg   = Y + (size_t)b * S * HIDDEN + h * DH;   // V_eff = y
    const float* padg = PAD + (size_t)b * S;

    // ---- load + convert Q tile (128 x 64), permuted column layout ----
    #pragma unroll
    for (int it = 0; it < 16; it++) {
        int idx = tid + 128 * it;            // 128 rows x 16 float4
        int row = idx >> 4, c4 = idx & 15;
        float4 v = *(const float4*)(Qg + (size_t)(q0 + row) * HIDDEN + c4 * 4);
        uint32_t* d = Qs + row * SK + (c4 >> 1) * 8 + (c4 & 1);
        d[0] = f2tf(v.x); d[2] = f2tf(v.y); d[4] = f2tf(v.z); d[6] = f2tf(v.w);
    }

    float O[2][8][4];
    float mrow[2][2], lrow[2][2];
    #pragma unroll
    for (int mh = 0; mh < 2; mh++) {
        mrow[mh][0] = mrow[mh][1] = -1e30f;
        lrow[mh][0] = lrow[mh][1] = 0.f;
        #pragma unroll
        for (int nt = 0; nt < 8; nt++)
            #pragma unroll
            for (int j = 0; j < 4; j++) O[mh][nt][j] = 0.f;
    }

    const int nkt   = 2 * qt + 2;
    const int kdiag = 2 * qt;     // tiles >= this need the causal compare
    for (int kt = 0; kt < nkt; kt++) {
        __syncthreads();                      // prev iter's Ks/Vs readers done
        const int k0 = kt * 64;

        // ---- load + convert K (permuted) / V (plain) tiles, neg-pad row ----
        #pragma unroll
        for (int it = 0; it < 8; it++) {
            int idx = tid + 128 * it;         // 64 rows x 16 float4
            int row = idx >> 4, c4 = idx & 15;
            float4 kv = *(const float4*)(Kg + (size_t)(k0 + row) * HIDDEN + c4 * 4);
            float4 vv = *(const float4*)(Vg + (size_t)(k0 + row) * HIDDEN + c4 * 4);
            uint32_t* dk = Ks + row * SK + (c4 >> 1) * 8 + (c4 & 1);
            dk[0] = f2tf(kv.x); dk[2] = f2tf(kv.y); dk[4] = f2tf(kv.z); dk[6] = f2tf(kv.w);
            uint4 pv;
            pv.x = f2tf(vv.x); pv.y = f2tf(vv.y); pv.z = f2tf(vv.z); pv.w = f2tf(vv.w);
            *(uint4*)(Vs + row * SK + c4 * 4) = pv;
        }
        if (tid < 16) {
            float4 pv = *(const float4*)(padg + k0 + tid * 4);
            float4 np;
            np.x = NEGBIG * (1.f - pv.x); np.y = NEGBIG * (1.f - pv.y);
            np.z = NEGBIG * (1.f - pv.z); np.w = NEGBIG * (1.f - pv.w);
            *(float4*)(npS + tid * 4) = np;
        }
        __syncthreads();

        const bool diag = (kt >= kdiag);
        uint32_t p[2][8][4];    // P tiles in tf32, score-C fragment layout

        #pragma unroll
        for (int mh = 0; mh < 2; mh++) {
            // ---- QK GEMM: c = Q(16x64) @ K^T -> 16x64 ----
            float c[8][4];
            #pragma unroll
            for (int nt = 0; nt < 8; nt++)
                #pragma unroll
                for (int j = 0; j < 4; j++) c[nt][j] = 0.f;

            const uint32_t* qb = Qs + (rbw + mh * 16 + g) * SK + 2 * l4;
            #pragma unroll
            for (int k8 = 0; k8 < 8; k8++) {
                uint2 t0 = *(const uint2*)(qb + k8 * 8);
                uint2 t1 = *(const uint2*)(qb + 8 * SK + k8 * 8);
                #pragma unroll
                for (int nt = 0; nt < 8; nt++) {
                    const uint2 bk = *(const uint2*)(Ks + (nt * 8 + g) * SK + k8 * 8 + 2 * l4);
                    mma8(c[nt], t0.x, t1.x, t0.y, t1.y, bk.x, bk.y);
                }
            }

            // ---- scale + mask + online softmax; emit P fragments ----
            #pragma unroll
            for (int h2 = 0; h2 < 2; h2++) {
                const int q = q0 + rbw + mh * 16 + 8 * h2 + g;
                float mx = -1e30f;
                #pragma unroll
                for (int nt = 0; nt < 8; nt++) {
                    #pragma unroll
                    for (int d = 0; d < 2; d++) {
                        int kcl = nt * 8 + 2 * l4 + d;
                        float add = npS[kcl];
                        if (diag && (k0 + kcl > q)) add = NEGBIG;
                        float val = fmaf(c[nt][2 * h2 + d], QSCALE, add);
                        c[nt][2 * h2 + d] = val;
                        mx = fmaxf(mx, val);
                    }
                }
                mx = fmaxf(mx, __shfl_xor_sync(0xffffffffu, mx, 1));
                mx = fmaxf(mx, __shfl_xor_sync(0xffffffffu, mx, 2));
                float mnew  = fmaxf(mrow[mh][h2], mx);
                float alpha = __expf(mrow[mh][h2] - mnew);
                mrow[mh][h2] = mnew;

                float rs = 0.f;
                #pragma unroll
                for (int nt = 0; nt < 8; nt++) {
                    #pragma unroll
                    for (int d = 0; d < 2; d++) {
                        float pf = __expf(c[nt][2 * h2 + d] - mnew);
                        rs += pf;
                        p[mh][nt][2 * h2 + d] = f2tf(pf);
                    }
                }
                rs += __shfl_xor_sync(0xffffffffu, rs, 1);
                rs += __shfl_xor_sync(0xffffffffu, rs, 2);
                lrow[mh][h2] = lrow[mh][h2] * alpha + rs;

                #pragma unroll
                for (int nt = 0; nt < 8; nt++) {
                    O[mh][nt][2 * h2]     *= alpha;
                    O[mh][nt][2 * h2 + 1] *= alpha;
                }
            }
        }

        // ---- PV GEMM (fused over mh): O += P(32x64) @ V(64x64) ----
        #pragma unroll
        for (int k8 = 0; k8 < 8; k8++) {
            uint32_t A[2][4];
            #pragma unroll
            for (int mh = 0; mh < 2; mh++) {
                uint32_t c0 = p[mh][k8][0], c1 = p[mh][k8][1];
                uint32_t c2 = p[mh][k8][2], c3 = p[mh][k8][3];
                uint32_t x0 = __shfl_sync(0xffffffffu, c0, src0);
                uint32_t x1 = __shfl_sync(0xffffffffu, c1, src0);
                uint32_t y0 = __shfl_sync(0xffffffffu, c2, src0);
                uint32_t y1 = __shfl_sync(0xffffffffu, c3, src0);
                uint32_t z0 = __shfl_sync(0xffffffffu, c0, src2);
                uint32_t z1 = __shfl_sync(0xffffffffu, c1, src2);
                uint32_t w0 = __shfl_sync(0xffffffffu, c2, src2);
                uint32_t w1 = __shfl_sync(0xffffffffu, c3, src2);
                A[mh][0] = dsel ? x1 : x0;
                A[mh][1] = dsel ? y1 : y0;
                A[mh][2] = dsel ? z1 : z0;
                A[mh][3] = dsel ? w1 : w0;
            }
            const uint32_t* vb0 = Vs + (k8 * 8 + l4) * SK + g;
            const uint32_t* vb1 = vb0 + 4 * SK;
            #pragma unroll
            for (int nt = 0; nt < 8; nt++) {
                uint32_t b0 = vb0[nt * 8];
                uint32_t b1 = vb1[nt * 8];
                mma8(O[0][nt], A[0][0], A[0][1], A[0][2], A[0][3], b0, b1);
                mma8(O[1][nt], A[1][0], A[1][1], A[1][2], A[1][3], b0, b1);
            }
        }
    }

    // ---- epilogue: normalize and store ----
    float* Og = OUT + (size_t)b * S * HIDDEN + h * DH;
    #pragma unroll
    for (int mh = 0; mh < 2; mh++) {
        #pragma unroll
        for (int h2 = 0; h2 < 2; h2++) {
            float inv = 1.f / lrow[mh][h2];
            int row = q0 + rbw + mh * 16 + 8 * h2 + g;
            #pragma unroll
            for (int nt = 0; nt < 8; nt++) {
                float2 o;
                o.x = O[mh][nt][2 * h2]     * inv;
                o.y = O[mh][nt][2 * h2 + 1] * inv;
                *(float2*)(Og + (size_t)row * HIDDEN + nt * 8 + 2 * l4) = o;
            }
        }
    }
}

extern "C" void kernel_launch(void* const* d_in, const int* in_sizes, int n_in,
                              void* d_out, int out_size)
{
    const float* x   = (const float*)d_in[0];
    const float* y   = (const float*)d_in[1];
    const float* z   = (const float*)d_in[2];
    const float* pad = (const float*)d_in[3];
    float* out = (float*)d_out;

    const int S = SEQ;
    const int B = in_sizes[3] / S;

    const size_t smem_bytes = (size_t)(128 + 64 + 64) * SK * sizeof(uint32_t)
                            + 64 * sizeof(float);          // 73,984 B -> 3 CTAs/SM
    cudaFuncSetAttribute(fa_tf32_kernel,
                         cudaFuncAttributeMaxDynamicSharedMemorySize,
                         (int)smem_bytes);

    dim3 grid(S / 128, HEADS, B);
    fa_tf32_kernel<<<grid, 128, smem_bytes>>>(x, y, z, pad, out, S);
}